// round 14
// baseline (speedup 1.0000x reference)
#include <cuda_runtime.h>
#include <math.h>

// ---------------- problem constants ----------------
constexpr int N_NODES = 10000;
constexpr int N_EDGES = 160000;
constexpr int B       = 8;
constexpr int T_IN    = 12;
constexpr int HP      = 64;
constexpr int HV      = 32;
constexpr int HVP     = HV / 2;       // 16 hidden-unit pairs
constexpr int NB      = N_NODES * B;  // 80000
constexpr int EB      = N_EDGES * B;  // 1280000

// ---------------- device scratch (static; no allocation) ----------------
__device__ float4 g_node[NB];       // per (node,b): P, R, S, Q
__device__ float4 g_ad4[EB / 2];    // per item-pair: (ex0, ds0, ex1, ds1)
__device__ float  g_den[NB];        // softmax denominator

// ---------------- packed f32x2 helpers ----------------
using U64 = unsigned long long;

__device__ __forceinline__ void ffma2_acc(U64& c, U64 a, U64 b) {
    asm("fma.rn.f32x2 %0, %1, %2, %0;" : "+l"(c) : "l"(a), "l"(b));
}
__device__ __forceinline__ void add2_acc(U64& c, U64 a) {
    asm("add.rn.f32x2 %0, %0, %1;" : "+l"(c) : "l"(a));
}
__device__ __forceinline__ U64 mul2(U64 a, U64 b) {
    U64 d;
    asm("mul.rn.f32x2 %0, %1, %2;" : "=l"(d) : "l"(a), "l"(b));
    return d;
}
__device__ __forceinline__ U64 pack2(float lo, float hi) {
    U64 d;
    asm("mov.b64 %0, {%1, %2};" : "=l"(d) : "f"(lo), "f"(hi));
    return d;
}
__device__ __forceinline__ void unpack2(U64 v, float& lo, float& hi) {
    asm("mov.b64 {%0, %1}, %2;" : "=f"(lo), "=f"(hi) : "l"(v));
}
__device__ __forceinline__ float f4c(float4 v, int c) {
    return c == 0 ? v.x : c == 1 ? v.y : c == 2 ? v.z : v.w;
}
__device__ __forceinline__ void prefetchL1(const void* p) {
    asm volatile("prefetch.global.L1 [%0];" :: "l"(p));
}

// ---------------- node kernel: fold z into (P,R,S,Q); also zero out/den -----------
__global__ __launch_bounds__(128)
void node_kernel(const float* __restrict__ feat,
                 const float* __restrict__ fcw,
                 const float* __restrict__ ln2g,
                 const float* __restrict__ attnw,
                 float* __restrict__ out) {
    __shared__ float sw[HP * T_IN];   // 768
    __shared__ float sgw[2 * HP];     // 128
    int tid = threadIdx.x;
    for (int i = tid; i < HP * T_IN; i += blockDim.x) sw[i] = fcw[i];
    if (tid < 2 * HP) sgw[tid] = ln2g[tid] * attnw[tid];
    __syncthreads();

    int t = blockIdx.x * blockDim.x + tid;   // grid covers NB exactly
    out[t]   = 0.f;
    g_den[t] = 0.f;

    float fr[T_IN];
    {
        const float4* f4 = reinterpret_cast<const float4*>(feat) + (size_t)t * 3;
        float4 a0 = f4[0], a1 = f4[1], a2 = f4[2];
        fr[0]=a0.x; fr[1]=a0.y; fr[2]=a0.z;  fr[3]=a0.w;
        fr[4]=a1.x; fr[5]=a1.y; fr[6]=a1.z;  fr[7]=a1.w;
        fr[8]=a2.x; fr[9]=a2.y; fr[10]=a2.z; fr[11]=a2.w;
    }

    float P = 0.f, R = 0.f, S = 0.f, Q = 0.f;
#pragma unroll
    for (int h = 0; h < HP; ++h) {
        float z = 0.f;
#pragma unroll
        for (int k = 0; k < T_IN; ++k) z = fmaf(sw[h * T_IN + k], fr[k], z);
        P = fmaf(z, sgw[h], P);
        R = fmaf(z, sgw[HP + h], R);
        S += z;
        Q = fmaf(z, z, Q);
    }
    g_node[t] = make_float4(P, R, S, Q);
}

// ---------------- velocity branch: 4 items per thread-pair, half hidden each --------
__device__ __forceinline__ float2 vbranch4(
    const ulonglong2* __restrict__ swt4,
    const U64* __restrict__ sb1v,
    const U64* __restrict__ slgv,
    const U64* __restrict__ slbv,
    const float2* __restrict__ sw2p,
    float b2,
    const float* __restrict__ inp, size_t base, int par) {

    const float4* f4 = reinterpret_cast<const float4*>(inp) + base * 3;

    int P8 = par * 8;
    U64 h[4][8];
#pragma unroll
    for (int jl = 0; jl < 8; ++jl) {
        U64 bb = sb1v[P8 + jl];
        h[0][jl] = bb; h[1][jl] = bb; h[2][jl] = bb; h[3][jl] = bb;
    }

#pragma unroll
    for (int cc = 0; cc < 3; ++cc) {
        float4 v0 = f4[0 * 3 + cc];
        float4 v1 = f4[1 * 3 + cc];
        float4 v2 = f4[2 * 3 + cc];
        float4 v3 = f4[3 * 3 + cc];
#pragma unroll
        for (int kk = 0; kk < 4; ++kk) {
            int k = cc * 4 + kk;
            ulonglong2 w0 = swt4[k * 8 + par * 4 + 0];
            ulonglong2 w1 = swt4[k * 8 + par * 4 + 1];
            ulonglong2 w2 = swt4[k * 8 + par * 4 + 2];
            ulonglong2 w3 = swt4[k * 8 + par * 4 + 3];

            float xf; U64 x;
            xf = f4c(v0, kk); x = pack2(xf, xf);
            ffma2_acc(h[0][0], w0.x, x); ffma2_acc(h[0][1], w0.y, x);
            ffma2_acc(h[0][2], w1.x, x); ffma2_acc(h[0][3], w1.y, x);
            ffma2_acc(h[0][4], w2.x, x); ffma2_acc(h[0][5], w2.y, x);
            ffma2_acc(h[0][6], w3.x, x); ffma2_acc(h[0][7], w3.y, x);
            xf = f4c(v1, kk); x = pack2(xf, xf);
            ffma2_acc(h[1][0], w0.x, x); ffma2_acc(h[1][1], w0.y, x);
            ffma2_acc(h[1][2], w1.x, x); ffma2_acc(h[1][3], w1.y, x);
            ffma2_acc(h[1][4], w2.x, x); ffma2_acc(h[1][5], w2.y, x);
            ffma2_acc(h[1][6], w3.x, x); ffma2_acc(h[1][7], w3.y, x);
            xf = f4c(v2, kk); x = pack2(xf, xf);
            ffma2_acc(h[2][0], w0.x, x); ffma2_acc(h[2][1], w0.y, x);
            ffma2_acc(h[2][2], w1.x, x); ffma2_acc(h[2][3], w1.y, x);
            ffma2_acc(h[2][4], w2.x, x); ffma2_acc(h[2][5], w2.y, x);
            ffma2_acc(h[2][6], w3.x, x); ffma2_acc(h[2][7], w3.y, x);
            xf = f4c(v3, kk); x = pack2(xf, xf);
            ffma2_acc(h[3][0], w0.x, x); ffma2_acc(h[3][1], w0.y, x);
            ffma2_acc(h[3][2], w1.x, x); ffma2_acc(h[3][3], w1.y, x);
            ffma2_acc(h[3][4], w2.x, x); ffma2_acc(h[3][5], w2.y, x);
            ffma2_acc(h[3][6], w3.x, x); ffma2_acc(h[3][7], w3.y, x);
        }
    }

    U64 nm2[4], iv2[4];
#pragma unroll
    for (int i = 0; i < 4; ++i) {
        U64 s = h[i][0];
        U64 q = pack2(0.f, 0.f);
        ffma2_acc(q, h[i][0], h[i][0]);
#pragma unroll
        for (int jl = 1; jl < 8; ++jl) {
            add2_acc(s, h[i][jl]);
            ffma2_acc(q, h[i][jl], h[i][jl]);
        }
        float sa, sb, qa, qb;
        unpack2(s, sa, sb); unpack2(q, qa, qb);
        float ps = sa + sb, pq = qa + qb;
        ps += __shfl_xor_sync(0xffffffffu, ps, 1);
        pq += __shfl_xor_sync(0xffffffffu, pq, 1);
        float m  = ps * (1.0f / HV);
        float iv = rsqrtf(fmaf(-m, m, pq * (1.0f / HV)) + 1e-5f);
        nm2[i] = pack2(-m, -m);
        iv2[i] = pack2(iv, iv);
    }

    float sp0 = 0.f, sp1 = 0.f, sp2 = 0.f, sp3 = 0.f;
#pragma unroll
    for (int jl = 0; jl < 8; ++jl) {
        U64 g  = slgv[P8 + jl];
        U64 bb = slbv[P8 + jl];
        float2 w2v = sw2p[P8 + jl];
        float ya, yb;

        add2_acc(h[0][jl], nm2[0]);
        { U64 sc = mul2(iv2[0], g); U64 y = bb; ffma2_acc(y, h[0][jl], sc);
          unpack2(y, ya, yb); ya = fmaxf(ya, 0.f); yb = fmaxf(yb, 0.f);
          sp0 = fmaf(ya, w2v.x, sp0); sp0 = fmaf(yb, w2v.y, sp0); }
        add2_acc(h[1][jl], nm2[1]);
        { U64 sc = mul2(iv2[1], g); U64 y = bb; ffma2_acc(y, h[1][jl], sc);
          unpack2(y, ya, yb); ya = fmaxf(ya, 0.f); yb = fmaxf(yb, 0.f);
          sp1 = fmaf(ya, w2v.x, sp1); sp1 = fmaf(yb, w2v.y, sp1); }
        add2_acc(h[2][jl], nm2[2]);
        { U64 sc = mul2(iv2[2], g); U64 y = bb; ffma2_acc(y, h[2][jl], sc);
          unpack2(y, ya, yb); ya = fmaxf(ya, 0.f); yb = fmaxf(yb, 0.f);
          sp2 = fmaf(ya, w2v.x, sp2); sp2 = fmaf(yb, w2v.y, sp2); }
        add2_acc(h[3][jl], nm2[3]);
        { U64 sc = mul2(iv2[3], g); U64 y = bb; ffma2_acc(y, h[3][jl], sc);
          unpack2(y, ya, yb); ya = fmaxf(ya, 0.f); yb = fmaxf(yb, 0.f);
          sp3 = fmaf(ya, w2v.x, sp3); sp3 = fmaf(yb, w2v.y, sp3); }
    }
    float s0 = sp0 + __shfl_xor_sync(0xffffffffu, sp0, 1) + b2;
    float s1 = sp1 + __shfl_xor_sync(0xffffffffu, sp1, 1) + b2;
    float s2 = sp2 + __shfl_xor_sync(0xffffffffu, sp2, 1) + b2;
    float s3 = sp3 + __shfl_xor_sync(0xffffffffu, sp3, 1) + b2;

    float sA = par ? s2 : s0;
    float sB = par ? s3 : s1;
    float2 o;
    o.x = __fdividef(1.0f, 1.0f + __expf(-sA));
    o.y = __fdividef(1.0f, 1.0f + __expf(-sB));
    return o;
}

// ---------------- fused kernel: vel-up + vel-dn + edge attention/diffusion ----------
struct FP {
    const float *up, *dn, *dist, *alpha, *feat;
    const int   *src, *dst;
    const float *w1u, *b1u, *lgu, *lbu, *w2u, *b2u;
    const float *w1d, *b1d, *lgd, *lbd, *w2d, *b2d;
    const float *l3w, *l3b;
    const float *ln2g, *ln2b, *attnw;
};

__global__ __launch_bounds__(128, 4)
void fused_kernel(FP p) {
    __shared__ __align__(16) float2 sWU[T_IN * HVP];
    __shared__ __align__(16) float2 sWD[T_IN * HVP];
    __shared__ __align__(8)  float2 sb1U[HVP], slgU[HVP], slbU[HVP], sw2U[HVP];
    __shared__ __align__(8)  float2 sb1D[HVP], slgD[HVP], slbD[HVP], sw2D[HVP];
    __shared__ float sb2s[2];
    __shared__ float c[7];

    int tid = threadIdx.x;

    // early: indices + scalars + prefetch of phase-3 gathers (lands under matvec)
    int    gid  = blockIdx.x * 128 + tid;        // gid < EB/2
    int    par  = tid & 1;
    size_t base = (size_t)(gid >> 1) * 4;
    int e  = gid >> 2;
    int b0 = (gid & 3) * 2;

    int   se   = p.src[e];
    int   de   = p.dst[e];
    float al   = p.alpha[e];
    float dste = p.dist[e];
    const float4* fptr = reinterpret_cast<const float4*>(p.feat) + ((size_t)se * B + b0) * 3;
    const float4* nsrc = &g_node[se * B + b0];
    const float4* ndst = &g_node[de * B + b0];
    prefetchL1(fptr);
    prefetchL1(fptr + 4);     // +64B covers the 96B span
    prefetchL1(nsrc);
    prefetchL1(ndst);

    // shared setup
    for (int i = tid; i < T_IN * HVP; i += 128) {
        int k  = i >> 4;
        int jp = i & 15;
        sWU[i] = make_float2(p.w1u[(2*jp)*T_IN + k], p.w1u[(2*jp+1)*T_IN + k]);
        sWD[i] = make_float2(p.w1d[(2*jp)*T_IN + k], p.w1d[(2*jp+1)*T_IN + k]);
    }
    if (tid < HVP) {
        int jp = tid;
        sb1U[jp] = make_float2(p.b1u[2*jp], p.b1u[2*jp+1]);
        slgU[jp] = make_float2(p.lgu[2*jp], p.lgu[2*jp+1]);
        slbU[jp] = make_float2(p.lbu[2*jp], p.lbu[2*jp+1]);
        sw2U[jp] = make_float2(p.w2u[2*jp], p.w2u[2*jp+1]);
    } else if (tid < 2 * HVP) {
        int jp = tid - HVP;
        sb1D[jp] = make_float2(p.b1d[2*jp], p.b1d[2*jp+1]);
        slgD[jp] = make_float2(p.lgd[2*jp], p.lgd[2*jp+1]);
        slbD[jp] = make_float2(p.lbd[2*jp], p.lbd[2*jp+1]);
        sw2D[jp] = make_float2(p.w2d[2*jp], p.w2d[2*jp+1]);
    } else if (tid >= 32 && tid < 64) {
        // warp 1: attention constants (G, C) reduction
        int lane = tid - 32;
        float gv = 0.f, cv = 0.f;
        for (int i = lane; i < 129; i += 32) {
            float w = p.attnw[i];
            gv = fmaf(p.ln2g[i], w, gv);
            cv = fmaf(p.ln2b[i], w, cv);
        }
#pragma unroll
        for (int o = 16; o; o >>= 1) {
            gv += __shfl_xor_sync(0xffffffffu, gv, o);
            cv += __shfl_xor_sync(0xffffffffu, cv, o);
        }
        if (lane == 0) {
            c[4] = p.ln2g[128] * p.attnw[128];
            c[5] = gv; c[6] = cv;
        }
    }
    if (tid == 64) {
        sb2s[0] = p.b2u[0]; sb2s[1] = p.b2d[0];
        c[0] = p.l3w[0]; c[1] = p.l3w[1]; c[2] = p.l3w[2]; c[3] = p.l3b[0];
    }
    __syncthreads();

    // phase 1 + 2: velocity branches
    float2 xu = vbranch4(reinterpret_cast<const ulonglong2*>(sWU),
                         reinterpret_cast<const U64*>(sb1U),
                         reinterpret_cast<const U64*>(slgU),
                         reinterpret_cast<const U64*>(slbU),
                         sw2U, sb2s[0], p.up, base, par);
    float2 xd = vbranch4(reinterpret_cast<const ulonglong2*>(sWD),
                         reinterpret_cast<const U64*>(sb1D),
                         reinterpret_cast<const U64*>(slgD),
                         reinterpret_cast<const U64*>(slbD),
                         sw2D, sb2s[1], p.dn, base, par);

    // phase 3: attention + diffusion (gathers now L1-resident)
    float alc = fminf(fmaxf(al, 0.f), 1.f);

    float f0[T_IN], f1[T_IN];
    {
        float4 q0 = fptr[0], q1 = fptr[1], q2 = fptr[2];
        float4 q3 = fptr[3], q4 = fptr[4], q5 = fptr[5];
        f0[0]=q0.x; f0[1]=q0.y; f0[2]=q0.z;  f0[3]=q0.w;
        f0[4]=q1.x; f0[5]=q1.y; f0[6]=q1.z;  f0[7]=q1.w;
        f0[8]=q2.x; f0[9]=q2.y; f0[10]=q2.z; f0[11]=q2.w;
        f1[0]=q3.x; f1[1]=q3.y; f1[2]=q3.z;  f1[3]=q3.w;
        f1[4]=q4.x; f1[5]=q4.y; f1[6]=q4.z;  f1[7]=q4.w;
        f1[8]=q5.x; f1[9]=q5.y; f1[10]=q5.z; f1[11]=q5.w;
    }

    float2 exo, dso;
#pragma unroll
    for (int i = 0; i < 2; ++i) {
        float xup = (i == 0) ? xu.x : xu.y;
        float xdn = (i == 0) ? xd.x : xd.y;
        const float* f = (i == 0) ? f0 : f1;

        float xv = c[0] * xup + c[1] * xdn + c[2] * al + c[3];
        float v = (xv > 0.f) ? (xv + __logf(1.0f + __expf(-xv)))
                             : __logf(1.0f + __expf(xv));
        v = fminf(v, 3.0f);
        float Tt = __fdividef(dste, v + 1e-5f);

        float Tidx = fminf(fmaxf(rintf(Tt * 0.1f), 0.0f), 11.0f);
        int   n    = T_IN - (int)Tidx;              // 1..12
        float F    = __fdividef(1.0f, 1.0f + alc * Tt);
        float omF  = 1.0f - F;

        float acc = 0.f, pw = 0.f;
#pragma unroll
        for (int k = T_IN - 1; k >= 0; --k) {
            if (k == n - 1) pw = F;
            if (k <= n - 1) { acc = fmaf(pw, f[k], acc); pw *= omF; }
        }

        float4 ns = nsrc[i];
        float4 nd = ndst[i];
        float Ssum = ns.z + nd.z + Tt;
        float m    = Ssum * (1.0f / 129.0f);
        float q    = ns.w + nd.w + Tt * Tt;
        float var  = q * (1.0f / 129.0f) - m * m;
        float dot  = ns.x + nd.y + Tt * c[4];
        float a    = (dot - m * c[5]) * rsqrtf(var + 1e-5f) + c[6];
        a = (a >= 0.f) ? a : 0.01f * a;             // leaky_relu

        float ex = __expf(a);
        if (i == 0) { exo.x = ex; dso.x = acc; }
        else        { exo.y = ex; dso.y = acc; }
        atomicAdd(&g_den[se * B + b0 + i], ex);
    }

    g_ad4[gid] = make_float4(exo.x, dso.x, exo.y, dso.y);
}

// ---------------- edge pass 3: pred[dst] += ex/den[src] * dsum ----------------
__global__ __launch_bounds__(256)
void edge3_kernel(const int* __restrict__ src, const int* __restrict__ dst,
                  float* __restrict__ out) {
    int t = blockIdx.x * 256 + threadIdx.x;
    int e = t >> 3, b = t & 7;
    float2 ad = reinterpret_cast<const float2*>(g_ad4)[t];
    float val = __fdividef(ad.x, g_den[src[e] * B + b]) * ad.y;
    atomicAdd(&out[dst[e] * B + b], val);
}

// ---------------- launch ----------------
extern "C" void kernel_launch(void* const* d_in, const int* in_sizes, int n_in,
                              void* d_out, int out_size) {
    bool sig_order = (n_in >= 6 && in_sizes[5] == HP * T_IN);   // fc_w=768 at idx 5

    int i_src, i_dst, i_alpha, i_fcw, i_ln2g, i_ln2b, i_attnw;
    int i_l11w, i_l11b, i_ln11g, i_ln11b, i_l12w, i_l12b;
    int i_l21w, i_l21b, i_ln21g, i_ln21b, i_l22w, i_l22b, i_l3w, i_l3b;

    if (!sig_order) {
        i_src = 4;  i_dst = 5;  i_alpha = 6;  i_fcw = 7;
        i_ln2g = 8; i_ln2b = 9; i_attnw = 10;
        i_l11w = 11; i_l11b = 12; i_ln11g = 13; i_ln11b = 14; i_l12w = 15; i_l12b = 16;
        i_l21w = 17; i_l21b = 18; i_ln21g = 19; i_ln21b = 20; i_l22w = 21; i_l22b = 22;
        i_l3w = 23;  i_l3b = 24;
    } else {
        i_alpha = 4; i_fcw = 5;
        i_ln2g = 6;  i_ln2b = 7; i_attnw = 8;
        i_l11w = 9;  i_l11b = 10; i_ln11g = 11; i_ln11b = 12; i_l12w = 13; i_l12b = 14;
        i_l21w = 15; i_l21b = 16; i_ln21g = 17; i_ln21b = 18; i_l22w = 19; i_l22b = 20;
        i_l3w = 21;  i_l3b = 22;  i_src = 23;   i_dst = 24;
    }

    const float* feat  = (const float*)d_in[0];
    const float* up    = (const float*)d_in[1];
    const float* dn    = (const float*)d_in[2];
    const float* dist  = (const float*)d_in[3];
    const float* alpha = (const float*)d_in[i_alpha];
    const int*   src   = (const int*)d_in[i_src];
    const int*   dst   = (const int*)d_in[i_dst];
    float* out = (float*)d_out;

    node_kernel<<<NB / 128, 128>>>(feat, (const float*)d_in[i_fcw],
                                   (const float*)d_in[i_ln2g],
                                   (const float*)d_in[i_attnw], out);

    FP p;
    p.up = up; p.dn = dn; p.dist = dist; p.alpha = alpha; p.feat = feat;
    p.src = src; p.dst = dst;
    p.w1u = (const float*)d_in[i_l11w]; p.b1u = (const float*)d_in[i_l11b];
    p.lgu = (const float*)d_in[i_ln11g]; p.lbu = (const float*)d_in[i_ln11b];
    p.w2u = (const float*)d_in[i_l12w]; p.b2u = (const float*)d_in[i_l12b];
    p.w1d = (const float*)d_in[i_l21w]; p.b1d = (const float*)d_in[i_l21b];
    p.lgd = (const float*)d_in[i_ln21g]; p.lbd = (const float*)d_in[i_ln21b];
    p.w2d = (const float*)d_in[i_l22w]; p.b2d = (const float*)d_in[i_l22b];
    p.l3w = (const float*)d_in[i_l3w];  p.l3b = (const float*)d_in[i_l3b];
    p.ln2g = (const float*)d_in[i_ln2g];
    p.ln2b = (const float*)d_in[i_ln2b];
    p.attnw = (const float*)d_in[i_attnw];

    fused_kernel<<<(EB / 2) / 128, 128>>>(p);

    edge3_kernel<<<EB / 256, 256>>>(src, dst, out);
}

// round 15
// speedup vs baseline: 1.6156x; 1.6156x over previous
#include <cuda_runtime.h>
#include <math.h>

// ---------------- problem constants ----------------
constexpr int N_NODES = 10000;
constexpr int N_EDGES = 160000;
constexpr int B       = 8;
constexpr int T_IN    = 12;
constexpr int HP      = 64;
constexpr int HV      = 32;
constexpr int HVP     = HV / 2;       // 16 hidden-unit pairs
constexpr int NB      = N_NODES * B;  // 80000
constexpr int EB      = N_EDGES * B;  // 1280000

// ---------------- device scratch (static; no allocation) ----------------
__device__ float4 g_node[NB];       // per (node,b): P, R, S, Q
__device__ float4 g_ad4[EB / 2];    // per item-pair: (ex0, ds0, ex1, ds1)
__device__ float  g_den[NB];        // softmax denominator
__device__ float  g_c3[3];          // [0]=gw[128], [1]=sum(g*w), [2]=sum(b*w)

// ---------------- packed f32x2 helpers ----------------
using U64 = unsigned long long;

__device__ __forceinline__ void ffma2_acc(U64& c, U64 a, U64 b) {
    asm("fma.rn.f32x2 %0, %1, %2, %0;" : "+l"(c) : "l"(a), "l"(b));
}
__device__ __forceinline__ void add2_acc(U64& c, U64 a) {
    asm("add.rn.f32x2 %0, %0, %1;" : "+l"(c) : "l"(a));
}
__device__ __forceinline__ U64 mul2(U64 a, U64 b) {
    U64 d;
    asm("mul.rn.f32x2 %0, %1, %2;" : "=l"(d) : "l"(a), "l"(b));
    return d;
}
__device__ __forceinline__ U64 pack2(float lo, float hi) {
    U64 d;
    asm("mov.b64 %0, {%1, %2};" : "=l"(d) : "f"(lo), "f"(hi));
    return d;
}
__device__ __forceinline__ void unpack2(U64 v, float& lo, float& hi) {
    asm("mov.b64 {%0, %1}, %2;" : "=f"(lo), "=f"(hi) : "l"(v));
}
__device__ __forceinline__ float f4c(float4 v, int c) {
    return c == 0 ? v.x : c == 1 ? v.y : c == 2 ? v.z : v.w;
}

// ---------------- node kernel: fold z into (P,R,S,Q); zero out/den; compute c3 ------
__global__ __launch_bounds__(128)
void node_kernel(const float* __restrict__ feat,
                 const float* __restrict__ fcw,
                 const float* __restrict__ ln2g,
                 const float* __restrict__ ln2b,
                 const float* __restrict__ attnw,
                 float* __restrict__ out) {
    __shared__ float4 sw4[HP * 3];    // weight rows as float4 (192 x 16B = 3 KB)
    __shared__ float  sgw[2 * HP];
    int tid = threadIdx.x;
    {
        const float4* w4 = reinterpret_cast<const float4*>(fcw);
        for (int i = tid; i < HP * 3; i += 128) sw4[i] = w4[i];
    }
    sgw[tid] = ln2g[tid] * attnw[tid];   // covers 0..127 = 2*HP
    __syncthreads();

    int t = blockIdx.x * 128 + tid;      // grid covers NB exactly
    out[t]   = 0.f;
    g_den[t] = 0.f;

    float4 i0, i1, i2;
    {
        const float4* f4 = reinterpret_cast<const float4*>(feat) + (size_t)t * 3;
        i0 = f4[0]; i1 = f4[1]; i2 = f4[2];
    }

    float P = 0.f, R = 0.f, S = 0.f, Q = 0.f;
#pragma unroll
    for (int h = 0; h < HP; ++h) {
        float4 wa = sw4[3 * h], wb = sw4[3 * h + 1], wc = sw4[3 * h + 2];
        float z = 0.f;
        z = fmaf(wa.x, i0.x, z); z = fmaf(wa.y, i0.y, z);
        z = fmaf(wa.z, i0.z, z); z = fmaf(wa.w, i0.w, z);
        z = fmaf(wb.x, i1.x, z); z = fmaf(wb.y, i1.y, z);
        z = fmaf(wb.z, i1.z, z); z = fmaf(wb.w, i1.w, z);
        z = fmaf(wc.x, i2.x, z); z = fmaf(wc.y, i2.y, z);
        z = fmaf(wc.z, i2.z, z); z = fmaf(wc.w, i2.w, z);
        P = fmaf(z, sgw[h], P);
        R = fmaf(z, sgw[HP + h], R);
        S += z;
        Q = fmaf(z, z, Q);
    }
    g_node[t] = make_float4(P, R, S, Q);

    // block 0, warp 0: attention constants
    if (blockIdx.x == 0 && tid < 32) {
        float gv = 0.f, cv = 0.f;
        for (int i = tid; i < 129; i += 32) {
            float w = attnw[i];
            gv = fmaf(ln2g[i], w, gv);
            cv = fmaf(ln2b[i], w, cv);
        }
#pragma unroll
        for (int o = 16; o; o >>= 1) {
            gv += __shfl_xor_sync(0xffffffffu, gv, o);
            cv += __shfl_xor_sync(0xffffffffu, cv, o);
        }
        if (tid == 0) {
            g_c3[0] = ln2g[128] * attnw[128];
            g_c3[1] = gv;
            g_c3[2] = cv;
        }
    }
}

// ---------------- velocity branch: 4 items per thread-pair, half hidden each --------
__device__ __forceinline__ float2 vbranch4(
    const ulonglong2* __restrict__ swt4,   // [k*8 + jj] pair-of-pairs
    const U64* __restrict__ sb1v,
    const U64* __restrict__ slgv,
    const U64* __restrict__ slbv,
    const float2* __restrict__ sw2p,
    float b2,
    const float* __restrict__ inp, size_t base /* item base (4 items) */,
    int par /* tid&1 */) {

    // load 4 items' inputs (lanes overlap; warp coalescer dedups sectors)
    float4 in4[12];
    {
        const float4* f4 = reinterpret_cast<const float4*>(inp) + base * 3;
#pragma unroll
        for (int v = 0; v < 12; ++v) in4[v] = f4[v];
    }

    int P8 = par * 8;            // this thread's first hidden pair
    U64 h[4][8];
#pragma unroll
    for (int jl = 0; jl < 8; ++jl) {
        U64 bb = sb1v[P8 + jl];
        h[0][jl] = bb; h[1][jl] = bb; h[2][jl] = bb; h[3][jl] = bb;
    }

#pragma unroll
    for (int k = 0; k < T_IN; ++k) {
        ulonglong2 w0 = swt4[k * 8 + par * 4 + 0];
        ulonglong2 w1 = swt4[k * 8 + par * 4 + 1];
        ulonglong2 w2 = swt4[k * 8 + par * 4 + 2];
        ulonglong2 w3 = swt4[k * 8 + par * 4 + 3];
#pragma unroll
        for (int i = 0; i < 4; ++i) {
            float xf = f4c(in4[i * 3 + (k >> 2)], k & 3);
            U64 x = pack2(xf, xf);
            ffma2_acc(h[i][0], w0.x, x); ffma2_acc(h[i][1], w0.y, x);
            ffma2_acc(h[i][2], w1.x, x); ffma2_acc(h[i][3], w1.y, x);
            ffma2_acc(h[i][4], w2.x, x); ffma2_acc(h[i][5], w2.y, x);
            ffma2_acc(h[i][6], w3.x, x); ffma2_acc(h[i][7], w3.y, x);
        }
    }

    // partial LN stats over own 16 hidden, complete via partner exchange
    U64 nm2[4], iv2[4];
#pragma unroll
    for (int i = 0; i < 4; ++i) {
        U64 s = h[i][0];
        U64 q = pack2(0.f, 0.f);
        ffma2_acc(q, h[i][0], h[i][0]);
#pragma unroll
        for (int jl = 1; jl < 8; ++jl) {
            add2_acc(s, h[i][jl]);
            ffma2_acc(q, h[i][jl], h[i][jl]);
        }
        float sa, sb, qa, qb;
        unpack2(s, sa, sb); unpack2(q, qa, qb);
        float ps = sa + sb, pq = qa + qb;
        ps += __shfl_xor_sync(0xffffffffu, ps, 1);
        pq += __shfl_xor_sync(0xffffffffu, pq, 1);
        float m  = ps * (1.0f / HV);
        float iv = rsqrtf(fmaf(-m, m, pq * (1.0f / HV)) + 1e-5f);
        nm2[i] = pack2(-m, -m);
        iv2[i] = pack2(iv, iv);
    }

    // epilogue: partial dot over own hidden, complete via exchange
    float sp0 = 0.f, sp1 = 0.f, sp2 = 0.f, sp3 = 0.f;
#pragma unroll
    for (int jl = 0; jl < 8; ++jl) {
        U64 g  = slgv[P8 + jl];
        U64 bb = slbv[P8 + jl];
        float2 w2v = sw2p[P8 + jl];
        float ya, yb;

        add2_acc(h[0][jl], nm2[0]);
        { U64 sc = mul2(iv2[0], g); U64 y = bb; ffma2_acc(y, h[0][jl], sc);
          unpack2(y, ya, yb); ya = fmaxf(ya, 0.f); yb = fmaxf(yb, 0.f);
          sp0 = fmaf(ya, w2v.x, sp0); sp0 = fmaf(yb, w2v.y, sp0); }
        add2_acc(h[1][jl], nm2[1]);
        { U64 sc = mul2(iv2[1], g); U64 y = bb; ffma2_acc(y, h[1][jl], sc);
          unpack2(y, ya, yb); ya = fmaxf(ya, 0.f); yb = fmaxf(yb, 0.f);
          sp1 = fmaf(ya, w2v.x, sp1); sp1 = fmaf(yb, w2v.y, sp1); }
        add2_acc(h[2][jl], nm2[2]);
        { U64 sc = mul2(iv2[2], g); U64 y = bb; ffma2_acc(y, h[2][jl], sc);
          unpack2(y, ya, yb); ya = fmaxf(ya, 0.f); yb = fmaxf(yb, 0.f);
          sp2 = fmaf(ya, w2v.x, sp2); sp2 = fmaf(yb, w2v.y, sp2); }
        add2_acc(h[3][jl], nm2[3]);
        { U64 sc = mul2(iv2[3], g); U64 y = bb; ffma2_acc(y, h[3][jl], sc);
          unpack2(y, ya, yb); ya = fmaxf(ya, 0.f); yb = fmaxf(yb, 0.f);
          sp3 = fmaf(ya, w2v.x, sp3); sp3 = fmaf(yb, w2v.y, sp3); }
    }
    float s0 = sp0 + __shfl_xor_sync(0xffffffffu, sp0, 1) + b2;
    float s1 = sp1 + __shfl_xor_sync(0xffffffffu, sp1, 1) + b2;
    float s2 = sp2 + __shfl_xor_sync(0xffffffffu, sp2, 1) + b2;
    float s3 = sp3 + __shfl_xor_sync(0xffffffffu, sp3, 1) + b2;

    float sA = par ? s2 : s0;      // local item 2*par
    float sB = par ? s3 : s1;      // local item 2*par+1
    float2 o;
    o.x = __fdividef(1.0f, 1.0f + __expf(-sA));
    o.y = __fdividef(1.0f, 1.0f + __expf(-sB));
    return o;
}

// ---------------- fused kernel: vel-up + vel-dn + edge attention/diffusion ----------
struct FP {
    const float *up, *dn, *dist, *alpha, *feat;
    const int   *src, *dst;
    const float *w1u, *b1u, *lgu, *lbu, *w2u, *b2u;
    const float *w1d, *b1d, *lgd, *lbd, *w2d, *b2d;
    const float *l3w, *l3b;
};

__global__ __launch_bounds__(128)
void fused_kernel(FP p) {
    __shared__ __align__(16) float2 sWU[T_IN * HVP];   // 1.5 KB
    __shared__ __align__(16) float2 sWD[T_IN * HVP];   // 1.5 KB
    __shared__ __align__(8)  float2 sb1U[HVP], slgU[HVP], slbU[HVP], sw2U[HVP];
    __shared__ __align__(8)  float2 sb1D[HVP], slgD[HVP], slbD[HVP], sw2D[HVP];
    __shared__ float sb2s[2];
    __shared__ float c[7];

    int tid = threadIdx.x;
    for (int i = tid; i < T_IN * HVP; i += 128) {
        int k  = i >> 4;
        int jp = i & 15;
        sWU[i] = make_float2(p.w1u[(2*jp)*T_IN + k], p.w1u[(2*jp+1)*T_IN + k]);
        sWD[i] = make_float2(p.w1d[(2*jp)*T_IN + k], p.w1d[(2*jp+1)*T_IN + k]);
    }
    if (tid < HVP) {
        int jp = tid;
        sb1U[jp] = make_float2(p.b1u[2*jp], p.b1u[2*jp+1]);
        slgU[jp] = make_float2(p.lgu[2*jp], p.lgu[2*jp+1]);
        slbU[jp] = make_float2(p.lbu[2*jp], p.lbu[2*jp+1]);
        sw2U[jp] = make_float2(p.w2u[2*jp], p.w2u[2*jp+1]);
    } else if (tid < 2 * HVP) {
        int jp = tid - HVP;
        sb1D[jp] = make_float2(p.b1d[2*jp], p.b1d[2*jp+1]);
        slgD[jp] = make_float2(p.lgd[2*jp], p.lgd[2*jp+1]);
        slbD[jp] = make_float2(p.lbd[2*jp], p.lbd[2*jp+1]);
        sw2D[jp] = make_float2(p.w2d[2*jp], p.w2d[2*jp+1]);
    } else if (tid == 2 * HVP) {
        sb2s[0] = p.b2u[0]; sb2s[1] = p.b2d[0];
        c[0] = p.l3w[0]; c[1] = p.l3w[1]; c[2] = p.l3w[2]; c[3] = p.l3b[0];
        c[4] = g_c3[0]; c[5] = g_c3[1]; c[6] = g_c3[2];
    }
    __syncthreads();

    int    gid  = blockIdx.x * 128 + tid;        // gid < EB/2
    int    par  = tid & 1;
    size_t base = (size_t)(gid >> 1) * 4;        // item base for the thread pair

    // phase 1 + 2: velocity branches (this thread's 2 items = 2*gid, 2*gid+1)
    float2 xu = vbranch4(reinterpret_cast<const ulonglong2*>(sWU),
                         reinterpret_cast<const U64*>(sb1U),
                         reinterpret_cast<const U64*>(slgU),
                         reinterpret_cast<const U64*>(slbU),
                         sw2U, sb2s[0], p.up, base, par);
    float2 xd = vbranch4(reinterpret_cast<const ulonglong2*>(sWD),
                         reinterpret_cast<const U64*>(sb1D),
                         reinterpret_cast<const U64*>(slgD),
                         reinterpret_cast<const U64*>(slbD),
                         sw2D, sb2s[1], p.dn, base, par);

    // phase 3: attention + diffusion, items 2*gid, 2*gid+1 (same edge)
    size_t t = (size_t)gid;
    int e  = (int)(t >> 2);
    int b0 = ((int)t & 3) * 2;

    float al   = p.alpha[e];
    float dste = p.dist[e];
    float alc  = fminf(fmaxf(al, 0.f), 1.f);
    int se = p.src[e];
    int de = p.dst[e];

    float f0[T_IN], f1[T_IN];
    {
        const float4* f4 = reinterpret_cast<const float4*>(p.feat)
                           + ((size_t)se * B + b0) * 3;
        float4 q0 = f4[0], q1 = f4[1], q2 = f4[2];
        float4 q3 = f4[3], q4 = f4[4], q5 = f4[5];
        f0[0]=q0.x; f0[1]=q0.y; f0[2]=q0.z;  f0[3]=q0.w;
        f0[4]=q1.x; f0[5]=q1.y; f0[6]=q1.z;  f0[7]=q1.w;
        f0[8]=q2.x; f0[9]=q2.y; f0[10]=q2.z; f0[11]=q2.w;
        f1[0]=q3.x; f1[1]=q3.y; f1[2]=q3.z;  f1[3]=q3.w;
        f1[4]=q4.x; f1[5]=q4.y; f1[6]=q4.z;  f1[7]=q4.w;
        f1[8]=q5.x; f1[9]=q5.y; f1[10]=q5.z; f1[11]=q5.w;
    }
    const float4* nsrc = &g_node[se * B + b0];
    const float4* ndst = &g_node[de * B + b0];

    float2 exo, dso;
#pragma unroll
    for (int i = 0; i < 2; ++i) {
        float xup = (i == 0) ? xu.x : xu.y;
        float xdn = (i == 0) ? xd.x : xd.y;
        const float* f = (i == 0) ? f0 : f1;

        float xv = c[0] * xup + c[1] * xdn + c[2] * al + c[3];
        float v = (xv > 0.f) ? (xv + __logf(1.0f + __expf(-xv)))
                             : __logf(1.0f + __expf(xv));
        v = fminf(v, 3.0f);
        float Tt = __fdividef(dste, v + 1e-5f);

        float Tidx = fminf(fmaxf(rintf(Tt * 0.1f), 0.0f), 11.0f);
        int   n    = T_IN - (int)Tidx;              // 1..12
        float F    = __fdividef(1.0f, 1.0f + alc * Tt);
        float omF  = 1.0f - F;

        float acc = 0.f, pw = 0.f;
#pragma unroll
        for (int k = T_IN - 1; k >= 0; --k) {
            if (k == n - 1) pw = F;
            if (k <= n - 1) { acc = fmaf(pw, f[k], acc); pw *= omF; }
        }

        float4 ns = nsrc[i];
        float4 nd = ndst[i];
        float Ssum = ns.z + nd.z + Tt;
        float m    = Ssum * (1.0f / 129.0f);
        float q    = ns.w + nd.w + Tt * Tt;
        float var  = q * (1.0f / 129.0f) - m * m;
        float dot  = ns.x + nd.y + Tt * c[4];
        float a    = (dot - m * c[5]) * rsqrtf(var + 1e-5f) + c[6];
        a = (a >= 0.f) ? a : 0.01f * a;             // leaky_relu

        float ex = __expf(a);
        if (i == 0) { exo.x = ex; dso.x = acc; }
        else        { exo.y = ex; dso.y = acc; }
        atomicAdd(&g_den[se * B + b0 + i], ex);
    }

    g_ad4[gid] = make_float4(exo.x, dso.x, exo.y, dso.y);
}

// ---------------- edge pass 3: pred[dst] += ex/den[src] * dsum ----------------
__global__ __launch_bounds__(256)
void edge3_kernel(const int* __restrict__ src, const int* __restrict__ dst,
                  float* __restrict__ out) {
    int t = blockIdx.x * 256 + threadIdx.x;
    int e = t >> 3, b = t & 7;
    float2 ad = reinterpret_cast<const float2*>(g_ad4)[t];
    float val = __fdividef(ad.x, g_den[src[e] * B + b]) * ad.y;
    atomicAdd(&out[dst[e] * B + b], val);
}

// ---------------- launch ----------------
extern "C" void kernel_launch(void* const* d_in, const int* in_sizes, int n_in,
                              void* d_out, int out_size) {
    bool sig_order = (n_in >= 6 && in_sizes[5] == HP * T_IN);   // fc_w=768 at idx 5

    int i_src, i_dst, i_alpha, i_fcw, i_ln2g, i_ln2b, i_attnw;
    int i_l11w, i_l11b, i_ln11g, i_ln11b, i_l12w, i_l12b;
    int i_l21w, i_l21b, i_ln21g, i_ln21b, i_l22w, i_l22b, i_l3w, i_l3b;

    if (!sig_order) {
        i_src = 4;  i_dst = 5;  i_alpha = 6;  i_fcw = 7;
        i_ln2g = 8; i_ln2b = 9; i_attnw = 10;
        i_l11w = 11; i_l11b = 12; i_ln11g = 13; i_ln11b = 14; i_l12w = 15; i_l12b = 16;
        i_l21w = 17; i_l21b = 18; i_ln21g = 19; i_ln21b = 20; i_l22w = 21; i_l22b = 22;
        i_l3w = 23;  i_l3b = 24;
    } else {
        i_alpha = 4; i_fcw = 5;
        i_ln2g = 6;  i_ln2b = 7; i_attnw = 8;
        i_l11w = 9;  i_l11b = 10; i_ln11g = 11; i_ln11b = 12; i_l12w = 13; i_l12b = 14;
        i_l21w = 15; i_l21b = 16; i_ln21g = 17; i_ln21b = 18; i_l22w = 19; i_l22b = 20;
        i_l3w = 21;  i_l3b = 22;  i_src = 23;   i_dst = 24;
    }

    const float* feat  = (const float*)d_in[0];
    const float* up    = (const float*)d_in[1];
    const float* dn    = (const float*)d_in[2];
    const float* dist  = (const float*)d_in[3];
    const float* alpha = (const float*)d_in[i_alpha];
    const int*   src   = (const int*)d_in[i_src];
    const int*   dst   = (const int*)d_in[i_dst];
    float* out = (float*)d_out;

    node_kernel<<<NB / 128, 128>>>(feat, (const float*)d_in[i_fcw],
                                   (const float*)d_in[i_ln2g],
                                   (const float*)d_in[i_ln2b],
                                   (const float*)d_in[i_attnw], out);

    FP p;
    p.up = up; p.dn = dn; p.dist = dist; p.alpha = alpha; p.feat = feat;
    p.src = src; p.dst = dst;
    p.w1u = (const float*)d_in[i_l11w]; p.b1u = (const float*)d_in[i_l11b];
    p.lgu = (const float*)d_in[i_ln11g]; p.lbu = (const float*)d_in[i_ln11b];
    p.w2u = (const float*)d_in[i_l12w]; p.b2u = (const float*)d_in[i_l12b];
    p.w1d = (const float*)d_in[i_l21w]; p.b1d = (const float*)d_in[i_l21b];
    p.lgd = (const float*)d_in[i_ln21g]; p.lbd = (const float*)d_in[i_ln21b];
    p.w2d = (const float*)d_in[i_l22w]; p.b2d = (const float*)d_in[i_l22b];
    p.l3w = (const float*)d_in[i_l3w];  p.l3b = (const float*)d_in[i_l3b];

    fused_kernel<<<(EB / 2) / 128, 128>>>(p);

    edge3_kernel<<<EB / 256, 256>>>(src, dst, out);
}